// round 7
// baseline (speedup 1.0000x reference)
#include <cuda_runtime.h>
#include <cuda_bf16.h>
#include <math.h>
#include <stdint.h>

// loss = mean_i ||v0_i - v1_i|| + 0.5 * sum_views mean_i [ log(sum_{j!=i} exp(-d_ij)) - log(N-1) ]
// d_ij = max(sqrt(max(|zi|^2+|zj|^2-2 zi.zj, 0)), 1e-12)
//
// Warp-specialized persistent kernel (1 CTA/SM, 512 threads):
//   warps 0-7  : producers — bf16 mma.sync Gram mainloop (as R5), dump fp32
//                accumulator tiles to double-buffered smem staging.
//   warps 8-15 : consumers — sqrt/exp epilogue + row/col sums, overlapped with
//                the producers' next tile. Handshake via named barriers.
// Symmetric upper-tri 128x128 tiles; each tile feeds row AND col sums.

namespace {
constexpr int N  = 8192;
constexpr int D  = 256;
constexpr int BM = 128;
constexpr int NT = N / BM;               // 64
constexpr int NTRI = NT * (NT + 1) / 2;  // 2080
constexpr int NTILES = 2 * NTRI;         // 4160
constexpr int PCTAS  = 148;              // persistent, 1 CTA/SM
constexpr int THREADS = 512;

constexpr int KCHUNK  = 64;              // bf16 k per chunk
constexpr int NCHUNK  = D / KCHUNK;      // 4
constexpr int PITCHB  = 144;             // operand smem row pitch bytes
constexpr int TILEB   = BM * PITCHB;     // 18432 per operand tile
constexpr int BUFB    = 2 * TILEB;       // A + B per stage (36864)
// acc staging: 128 x 128 f32, pitch 132 floats (16B-aligned rows, low conflicts)
constexpr int APITCH  = 132;
constexpr int ACCB    = BM * APITCH * 4; // 67584
constexpr int SM_ACC  = 2 * BUFB;        // 73728
constexpr int SM_SQB  = SM_ACC + 2 * ACCB;  // 208896 (sqi[128] + sqj[128])
constexpr int SMEM_TOTAL = SM_SQB + 1024;   // 209920

// named barrier ids
constexpr int BAR_FULL0 = 1, BAR_FULL1 = 2;   // producers arrive, consumers sync (512)
constexpr int BAR_EMPTY0 = 3, BAR_EMPTY1 = 4; // consumers arrive, producers sync (512)
constexpr int BAR_PROD = 5;                    // producer-internal (256)
constexpr int BAR_CONS = 6;                    // consumer-internal (256)
}

__device__ __align__(16) __nv_bfloat16 g_bf[2][N][D];
__device__ __align__(16) float g_sq[2][N];
__device__ __align__(16) float g_alignRow[N];
__device__ __align__(16) float g_part[2][NT][N];

// ---------------- PTX helpers (stable ISA only) -----------------------------
__device__ __forceinline__ uint32_t smem_u32(const void* p) {
    uint32_t a;
    asm("{ .reg .u64 t; cvta.to.shared.u64 t, %1; cvt.u32.u64 %0, t; }" : "=r"(a) : "l"(p));
    return a;
}
__device__ __forceinline__ void cpasync16(uint32_t dst, const void* src) {
    asm volatile("cp.async.cg.shared.global [%0], [%1], 16;" :: "r"(dst), "l"(src) : "memory");
}
#define CP_COMMIT()  asm volatile("cp.async.commit_group;" ::: "memory")
#define CP_WAIT0()   asm volatile("cp.async.wait_group 0;" ::: "memory")

__device__ __forceinline__ void bar_sync(int id, int cnt) {
    asm volatile("bar.sync %0, %1;" :: "r"(id), "r"(cnt) : "memory");
}
__device__ __forceinline__ void bar_arrive(int id, int cnt) {
    asm volatile("bar.arrive %0, %1;" :: "r"(id), "r"(cnt) : "memory");
}

__device__ __forceinline__ void ldsm4(uint32_t* r, uint32_t addr) {
    asm volatile("ldmatrix.sync.aligned.m8n8.x4.shared.b16 {%0,%1,%2,%3}, [%4];"
                 : "=r"(r[0]), "=r"(r[1]), "=r"(r[2]), "=r"(r[3]) : "r"(addr));
}
__device__ __forceinline__ void mma16816(float* c, const uint32_t* a, uint32_t b0, uint32_t b1) {
    asm volatile(
        "mma.sync.aligned.m16n8k16.row.col.f32.bf16.bf16.f32 "
        "{%0,%1,%2,%3}, {%4,%5,%6,%7}, {%8,%9}, {%0,%1,%2,%3};"
        : "+f"(c[0]), "+f"(c[1]), "+f"(c[2]), "+f"(c[3])
        : "r"(a[0]), "r"(a[1]), "r"(a[2]), "r"(a[3]), "r"(b0), "r"(b1));
}
__device__ __forceinline__ float fsqrt_approx(float x) {
    float r; asm("sqrt.approx.f32 %0, %1;" : "=f"(r) : "f"(x)); return r;
}

__device__ __forceinline__ void decode_tile(int l, int& view, int& ti, int& tj) {
    view = (l >= NTRI) ? 1 : 0;
    int u = l - view * NTRI;
    int t = (int)((sqrtf(8.f * (float)u + 1.f) - 1.f) * 0.5f);
    while ((t + 1) * (t + 2) / 2 <= u) ++t;
    while (t * (t + 1) / 2 > u) --t;
    tj = t;
    ti = u - t * (t + 1) / 2;
}

// ---------------------------------------------------------------------------
// Kernel 1: fp32 -> bf16; squared norms (fp32); align row norms.
// ---------------------------------------------------------------------------
__global__ void convert_kernel(const float* __restrict__ v0, const float* __restrict__ v1) {
    int row  = blockIdx.x * blockDim.y + threadIdx.y;
    int lane = threadIdx.x;
    const float4* r0 = reinterpret_cast<const float4*>(v0 + (size_t)row * D);
    const float4* r1 = reinterpret_cast<const float4*>(v1 + (size_t)row * D);
    __nv_bfloat162* h0 = reinterpret_cast<__nv_bfloat162*>(&g_bf[0][row][0]);
    __nv_bfloat162* h1 = reinterpret_cast<__nv_bfloat162*>(&g_bf[1][row][0]);

    float s0 = 0.f, s1 = 0.f, sd = 0.f;
#pragma unroll
    for (int c = lane; c < D / 4; c += 32) {
        float4 a = r0[c], b = r1[c];
        s0 += a.x*a.x + a.y*a.y + a.z*a.z + a.w*a.w;
        s1 += b.x*b.x + b.y*b.y + b.z*b.z + b.w*b.w;
        float dx=a.x-b.x, dy=a.y-b.y, dz=a.z-b.z, dw=a.w-b.w;
        sd += dx*dx + dy*dy + dz*dz + dw*dw;
        h0[2*c]   = __halves2bfloat162(__float2bfloat16(a.x), __float2bfloat16(a.y));
        h0[2*c+1] = __halves2bfloat162(__float2bfloat16(a.z), __float2bfloat16(a.w));
        h1[2*c]   = __halves2bfloat162(__float2bfloat16(b.x), __float2bfloat16(b.y));
        h1[2*c+1] = __halves2bfloat162(__float2bfloat16(b.z), __float2bfloat16(b.w));
    }
#pragma unroll
    for (int off = 16; off > 0; off >>= 1) {
        s0 += __shfl_down_sync(0xffffffffu, s0, off);
        s1 += __shfl_down_sync(0xffffffffu, s1, off);
        sd += __shfl_down_sync(0xffffffffu, sd, off);
    }
    if (lane == 0) {
        g_sq[0][row] = s0;
        g_sq[1][row] = s1;
        g_alignRow[row] = sqrtf(sd);
    }
}

// ---------------------------------------------------------------------------
// Kernel 2: warp-specialized persistent Gram + epilogue.
// ---------------------------------------------------------------------------
__global__ __launch_bounds__(THREADS, 1)
void gram_ws_kernel() {
    extern __shared__ char smem[];
    const uint32_t sb = smem_u32(smem);
    const int tid = threadIdx.x;
    const int lid = tid & 31;
    const int wid = tid >> 5;
    const int bid = blockIdx.x;

    if (wid < 8) {
        // =================== PRODUCERS (warps 0-7, tid 0..255) ===============
        const int wm = wid >> 2;   // 0..1
        const int wn = wid & 3;    // 0..3

        // ldmatrix lane-invariant offsets
        const int rA = (lid & 7) | (((lid >> 3) & 1) << 3);
        const int cB = (lid >> 4) * 8;
        uint32_t aoff[4], boff[2];
#pragma unroll
        for (int mt = 0; mt < 4; mt++) aoff[mt] = (uint32_t)((wm*64 + mt*16 + rA) * PITCHB + cB*2);
#pragma unroll
        for (int np = 0; np < 2; np++) boff[np] = (uint32_t)((wn*32 + np*16 + rA) * PITCHB + cB*2);

        auto load_chunk = [&](int view, int i0, int j0, int c, int b) {
            const int kt = c * KCHUNK;
            const uint32_t base = sb + b * BUFB;
            const __nv_bfloat16* A = &g_bf[view][i0][0];
            const __nv_bfloat16* B = &g_bf[view][j0][0];
#pragma unroll
            for (int it = 0; it < 8; it++) {
                const int t   = it >> 2;
                const int rem = (it & 3) * 256 + tid;
                const int row = rem >> 3;
                const int u   = rem & 7;
                const __nv_bfloat16* src = (t == 0 ? A : B) + (size_t)row * D + kt + u * 8;
                cpasync16(base + t * TILEB + row * PITCHB + u * 16, src);
            }
            CP_COMMIT();
        };

        int l = bid;
        if (l >= NTILES) return;
        int view, ti, tj;
        decode_tile(l, view, ti, tj);
        int i0 = ti * BM, j0 = tj * BM;

        load_chunk(view, i0, j0, 0, 0);   // prime: chunk 0 of tile 0 -> buf 0

        int k = 0;
        while (true) {
            const int ln = l + PCTAS;
            const bool hn = (ln < NTILES);
            int viewn = 0, tin = 0, tjn = 0, i0n = 0, j0n = 0;
            if (hn) { decode_tile(ln, viewn, tin, tjn); i0n = tin * BM; j0n = tjn * BM; }

            float acc[4][4][4];
#pragma unroll
            for (int a = 0; a < 4; a++)
#pragma unroll
                for (int b = 0; b < 4; b++)
#pragma unroll
                    for (int q = 0; q < 4; q++) acc[a][b][q] = 0.f;

            for (int c = 0; c < NCHUNK; c++) {
                const int s = c & 1;   // 4 chunks/tile (even) -> parity independent of k
                CP_WAIT0();            // our chunk s has landed (1 group in flight max)
                bar_sync(BAR_PROD, 256);
                // issue next step's loads (overlap with compute below)
                if (c + 1 < NCHUNK)      load_chunk(view, i0, j0, c + 1, s ^ 1);
                else if (hn)             load_chunk(viewn, i0n, j0n, 0, s ^ 1);

                const uint32_t bA = sb + s * BUFB + 0 * TILEB;
                const uint32_t bB = sb + s * BUFB + 1 * TILEB;
#pragma unroll
                for (int ks = 0; ks < KCHUNK / 16; ks++) {
                    const uint32_t ko = ks * 32;
                    uint32_t A[4][4], B[2][4];
#pragma unroll
                    for (int mt = 0; mt < 4; mt++) ldsm4(A[mt], bA + aoff[mt] + ko);
#pragma unroll
                    for (int np = 0; np < 2; np++) ldsm4(B[np], bB + boff[np] + ko);
#pragma unroll
                    for (int mt = 0; mt < 4; mt++) {
#pragma unroll
                        for (int nt = 0; nt < 4; nt++) {
                            const int np = nt >> 1, sel = nt & 1;
                            mma16816(acc[mt][nt], A[mt], B[np][sel], B[np][2 + sel]);
                        }
                    }
                }
            }

            // dump accumulator to staging slot
            const int sa = k & 1;
            if (k >= 2) bar_sync(sa ? BAR_EMPTY1 : BAR_EMPTY0, 512);
            float* accb = reinterpret_cast<float*>(smem + SM_ACC + sa * ACCB);
#pragma unroll
            for (int mt = 0; mt < 4; mt++) {
                const int r1 = wm*64 + mt*16 + (lid >> 2);
#pragma unroll
                for (int nt = 0; nt < 4; nt++) {
                    const int c = wn*32 + nt*8 + 2*(lid & 3);
                    *reinterpret_cast<float2*>(&accb[r1*APITCH + c]) =
                        make_float2(acc[mt][nt][0], acc[mt][nt][1]);
                    *reinterpret_cast<float2*>(&accb[(r1+8)*APITCH + c]) =
                        make_float2(acc[mt][nt][2], acc[mt][nt][3]);
                }
            }
            bar_arrive(sa ? BAR_FULL1 : BAR_FULL0, 512);

            if (!hn) break;
            l = ln; view = viewn; ti = tin; tj = tjn; i0 = i0n; j0 = j0n; ++k;
        }
    } else {
        // =================== CONSUMERS (warps 8-15, tid 256..511) ============
        const int tid2 = tid - 256;
        float* sqib = reinterpret_cast<float*>(smem + SM_SQB);
        float* sqjb = sqib + 128;

        int l = bid;
        int k = 0;
        while (l < NTILES) {
            int view, ti, tj;
            decode_tile(l, view, ti, tj);
            const int i0 = ti * BM, j0 = tj * BM;
            const int sa = k & 1;

            bar_sync(sa ? BAR_FULL1 : BAR_FULL0, 512);   // acc slot ready

            // stage squared norms
            if (tid2 < 128) sqib[tid2] = g_sq[view][i0 + tid2];
            else            sqjb[tid2 - 128] = g_sq[view][j0 + tid2 - 128];
            bar_sync(BAR_CONS, 256);

            float* accb = reinterpret_cast<float*>(smem + SM_ACC + sa * ACCB);
            const bool diag = (ti == tj);

            // pass 1: rows. thread -> (row, col half); e stored in place.
            {
                const int r  = tid2 >> 1;
                const int c0 = (tid2 & 1) * 64;
                const float sqi = sqib[r];
                float rsum = 0.f;
#pragma unroll
                for (int cc = 0; cc < 16; cc++) {
                    float4 dv = *reinterpret_cast<float4*>(&accb[r*APITCH + c0 + cc*4]);
                    float e[4];
#pragma unroll
                    for (int q = 0; q < 4; q++) {
                        const int c = c0 + cc*4 + q;
                        const float dot = (q == 0 ? dv.x : q == 1 ? dv.y : q == 2 ? dv.z : dv.w);
                        float d2 = fmaxf(sqi + sqjb[c] - 2.f * dot, 0.f);
                        float d  = fsqrt_approx(d2);
                        float ev = (diag && c == r) ? 0.f : __expf(-d);
                        e[q] = ev;
                        rsum += ev;
                    }
                    *reinterpret_cast<float4*>(&accb[r*APITCH + c0 + cc*4]) =
                        make_float4(e[0], e[1], e[2], e[3]);
                }
                rsum += __shfl_xor_sync(0xffffffffu, rsum, 1);
                if ((tid2 & 1) == 0) g_part[view][tj][i0 + r] = rsum;
            }
            bar_sync(BAR_CONS, 256);

            // pass 2: columns (skip for diagonal tiles).
            if (!diag) {
                const int c  = tid2 >> 1;
                const int r0 = (tid2 & 1) * 64;
                float cs0 = 0.f, cs1 = 0.f, cs2 = 0.f, cs3 = 0.f;
#pragma unroll
                for (int rr = 0; rr < 64; rr += 4) {
                    cs0 += accb[(r0 + rr + 0)*APITCH + c];
                    cs1 += accb[(r0 + rr + 1)*APITCH + c];
                    cs2 += accb[(r0 + rr + 2)*APITCH + c];
                    cs3 += accb[(r0 + rr + 3)*APITCH + c];
                }
                float cs = (cs0 + cs1) + (cs2 + cs3);
                cs += __shfl_xor_sync(0xffffffffu, cs, 1);
                if ((tid2 & 1) == 0) g_part[view][ti][j0 + c] = cs;
            }
            bar_arrive(sa ? BAR_EMPTY1 : BAR_EMPTY0, 512);

            l += PCTAS; ++k;
        }
    }
}

// ---------------------------------------------------------------------------
// Kernel 3: finalize with fp64 accumulation.
// ---------------------------------------------------------------------------
__global__ void finalize_kernel(float* __restrict__ out) {
    __shared__ double sh0[256], sh1[256], sh2[256];
    const int tid = threadIdx.x;
    double a = 0.0, e0 = 0.0, e1 = 0.0;
    for (int i = tid; i < N; i += 256) {
        a += (double)g_alignRow[i];
        float s0 = 0.f, s1 = 0.f;
#pragma unroll
        for (int c = 0; c < NT; c++) {
            s0 += g_part[0][c][i];
            s1 += g_part[1][c][i];
        }
        e0 += log((double)s0);
        e1 += log((double)s1);
    }
    sh0[tid] = a; sh1[tid] = e0; sh2[tid] = e1;
    __syncthreads();
    for (int off = 128; off > 0; off >>= 1) {
        if (tid < off) {
            sh0[tid] += sh0[tid + off];
            sh1[tid] += sh1[tid + off];
            sh2[tid] += sh2[tid + off];
        }
        __syncthreads();
    }
    if (tid == 0) {
        const double inv_n = 1.0 / (double)N;
        const double logm  = log((double)(N - 1));
        double align   = sh0[0] * inv_n;
        double entropy = 0.5 * ((sh1[0] * inv_n - logm) + (sh2[0] * inv_n - logm));
        out[0] = (float)(align + entropy);
    }
}

// ---------------------------------------------------------------------------
extern "C" void kernel_launch(void* const* d_in, const int* in_sizes, int n_in,
                              void* d_out, int out_size) {
    const float* v0 = (const float*)d_in[0];
    const float* v1 = (const float*)d_in[1];
    float* out = (float*)d_out;

    cudaFuncSetAttribute(gram_ws_kernel, cudaFuncAttributeMaxDynamicSharedMemorySize, SMEM_TOTAL);

    convert_kernel<<<N / 8, dim3(32, 8)>>>(v0, v1);
    gram_ws_kernel<<<PCTAS, THREADS, SMEM_TOTAL>>>();
    finalize_kernel<<<1, 256>>>(out);
}

// round 8
// speedup vs baseline: 1.0739x; 1.0739x over previous
#include <cuda_runtime.h>
#include <cuda_bf16.h>
#include <math.h>
#include <stdint.h>

// loss = mean_i ||v0_i - v1_i|| + 0.5 * sum_views mean_i [ log(sum_{j!=i} exp(-d_ij)) - log(N-1) ]
// d_ij = max(sqrt(max(|zi|^2+|zj|^2-2 zi.zj, 0)), 1e-12)
//
// Gram via mma.sync pure bf16 (verified rel_err ~1.3e-5).
// 128x256 SUPERTILES: one CTA (512 thr, 16 warps, warp grid 2Mx8N) computes two
// adjacent 128x128 column tiles; A staged once for both. Symmetric: supertile
// (ti, tJ) covers sub-tiles (ti, 2tJ) [valid if ti<=2tJ] and (ti, 2tJ+1)
// [always valid]; each valid sub-tile feeds row sums AND col sums (slots as R5).

namespace {
constexpr int N  = 8192;
constexpr int D  = 256;
constexpr int BM = 128;
constexpr int NT = N / BM;                // 64 col tiles
constexpr int NTJ = NT / 2;               // 32 supertile cols
// supertiles per view: sum_{tJ=0..30} (2tJ+2) + 64 = 992 + 64 = 1056
constexpr int NSUP = 1056;

constexpr int THREADS = 512;
constexpr int KCHUNK  = 64;               // bf16 k per chunk
constexpr int NCHUNK  = D / KCHUNK;       // 4
constexpr int PITCHB  = 144;              // smem row pitch bytes
constexpr int A_TILEB = BM * PITCHB;      // 18432
constexpr int B_TILEB = 2 * BM * PITCHB;  // 36864 (256 rows)
constexpr int STAGEB  = A_TILEB + B_TILEB; // 55296
constexpr int SM_SQI  = 2 * STAGEB;       // 110592 (128 f32)
constexpr int SM_SQJ  = SM_SQI + 512;     // (256 f32)
constexpr int SM_ROW  = SM_SQJ + 1024;    // [8][128] f32 = 4096
constexpr int SM_COL  = SM_ROW + 4096;    // [2][256] f32 = 2048
constexpr int SMEM_TOTAL = SM_COL + 2048 + 256;  // ~118KB -> 1 CTA/SM
}

__device__ __align__(16) __nv_bfloat16 g_bf[2][N][D];
__device__ __align__(16) float g_sq[2][N];
__device__ __align__(16) float g_alignRow[N];
__device__ __align__(16) float g_part[2][NT][N];

// ---------------- PTX helpers (stable ISA only) -----------------------------
__device__ __forceinline__ uint32_t smem_u32(const void* p) {
    uint32_t a;
    asm("{ .reg .u64 t; cvta.to.shared.u64 t, %1; cvt.u32.u64 %0, t; }" : "=r"(a) : "l"(p));
    return a;
}
__device__ __forceinline__ void cpasync16(uint32_t dst, const void* src) {
    asm volatile("cp.async.cg.shared.global [%0], [%1], 16;" :: "r"(dst), "l"(src) : "memory");
}
#define CP_COMMIT()  asm volatile("cp.async.commit_group;" ::: "memory")
#define CP_WAIT(n)   asm volatile("cp.async.wait_group %0;" :: "n"(n) : "memory")

__device__ __forceinline__ void ldsm4(uint32_t* r, uint32_t addr) {
    asm volatile("ldmatrix.sync.aligned.m8n8.x4.shared.b16 {%0,%1,%2,%3}, [%4];"
                 : "=r"(r[0]), "=r"(r[1]), "=r"(r[2]), "=r"(r[3]) : "r"(addr));
}
__device__ __forceinline__ void mma16816(float* c, const uint32_t* a, uint32_t b0, uint32_t b1) {
    asm volatile(
        "mma.sync.aligned.m16n8k16.row.col.f32.bf16.bf16.f32 "
        "{%0,%1,%2,%3}, {%4,%5,%6,%7}, {%8,%9}, {%0,%1,%2,%3};"
        : "+f"(c[0]), "+f"(c[1]), "+f"(c[2]), "+f"(c[3])
        : "r"(a[0]), "r"(a[1]), "r"(a[2]), "r"(a[3]), "r"(b0), "r"(b1));
}
__device__ __forceinline__ float fsqrt_approx(float x) {
    float r; asm("sqrt.approx.f32 %0, %1;" : "=f"(r) : "f"(x)); return r;
}

// supertile decode: within a view, l indexes (tJ, ti) with ti < min(2tJ+2, 64).
// cum(tJ) = tJ^2 + tJ for tJ <= 31 (since 2tJ+2 <= 64 for tJ <= 31).
__device__ __forceinline__ void decode_super(int u, int& ti, int& tJ) {
    int t = (int)((sqrtf(4.f * (float)u + 1.f) - 1.f) * 0.5f);
    while ((t + 1) * (t + 2) <= u) ++t;    // cum(t+1) = (t+1)^2+(t+1) = (t+1)(t+2)
    while (t * (t + 1) > u) --t;
    tJ = t;
    ti = u - t * (t + 1);
}

// ---------------------------------------------------------------------------
// Kernel 1: fp32 -> bf16; squared norms (fp32); align row norms.
// ---------------------------------------------------------------------------
__global__ void convert_kernel(const float* __restrict__ v0, const float* __restrict__ v1) {
    int row  = blockIdx.x * blockDim.y + threadIdx.y;
    int lane = threadIdx.x;
    const float4* r0 = reinterpret_cast<const float4*>(v0 + (size_t)row * D);
    const float4* r1 = reinterpret_cast<const float4*>(v1 + (size_t)row * D);
    __nv_bfloat162* h0 = reinterpret_cast<__nv_bfloat162*>(&g_bf[0][row][0]);
    __nv_bfloat162* h1 = reinterpret_cast<__nv_bfloat162*>(&g_bf[1][row][0]);

    float s0 = 0.f, s1 = 0.f, sd = 0.f;
#pragma unroll
    for (int c = lane; c < D / 4; c += 32) {
        float4 a = r0[c], b = r1[c];
        s0 += a.x*a.x + a.y*a.y + a.z*a.z + a.w*a.w;
        s1 += b.x*b.x + b.y*b.y + b.z*b.z + b.w*b.w;
        float dx=a.x-b.x, dy=a.y-b.y, dz=a.z-b.z, dw=a.w-b.w;
        sd += dx*dx + dy*dy + dz*dz + dw*dw;
        h0[2*c]   = __halves2bfloat162(__float2bfloat16(a.x), __float2bfloat16(a.y));
        h0[2*c+1] = __halves2bfloat162(__float2bfloat16(a.z), __float2bfloat16(a.w));
        h1[2*c]   = __halves2bfloat162(__float2bfloat16(b.x), __float2bfloat16(b.y));
        h1[2*c+1] = __halves2bfloat162(__float2bfloat16(b.z), __float2bfloat16(b.w));
    }
#pragma unroll
    for (int off = 16; off > 0; off >>= 1) {
        s0 += __shfl_down_sync(0xffffffffu, s0, off);
        s1 += __shfl_down_sync(0xffffffffu, s1, off);
        sd += __shfl_down_sync(0xffffffffu, sd, off);
    }
    if (lane == 0) {
        g_sq[0][row] = s0;
        g_sq[1][row] = s1;
        g_alignRow[row] = sqrtf(sd);
    }
}

// ---------------------------------------------------------------------------
// Kernel 2: 128x256 supertile Gram + exp(-d) row/col sums via mma.sync bf16.
// 512 threads = 16 warps, warp grid 2(M) x 8(N). Warp tile 64x32 (as R5).
// ---------------------------------------------------------------------------
__global__ __launch_bounds__(THREADS, 1)
void gram_mma_kernel() {
    extern __shared__ char smem[];
    const uint32_t sb = smem_u32(smem);
    const int tid = threadIdx.x;
    const int lid = tid & 31;
    const int wid = tid >> 5;
    const int wm = wid >> 3;          // 0..1  (M)
    const int wn = wid & 7;           // 0..7  (N over 256 cols)
    const int view = blockIdx.z;

    int ti, tJ;
    decode_super(blockIdx.x, ti, tJ);
    const int i0 = ti * BM;
    const int j0 = tJ * 256;
    const int tj0 = 2 * tJ, tj1 = 2 * tJ + 1;
    const bool sub0_valid = (ti <= tj0);
    const bool diag0 = (ti == tj0);
    const bool diag1 = (ti == tj1);

    const __nv_bfloat16* __restrict__ Aptr = &g_bf[view][i0][0];
    const __nv_bfloat16* __restrict__ Bptr = &g_bf[view][j0][0];

    float* sqi_s = reinterpret_cast<float*>(smem + SM_SQI);   // [128]
    float* sqj_s = reinterpret_cast<float*>(smem + SM_SQJ);   // [256]
    float* s_row = reinterpret_cast<float*>(smem + SM_ROW);   // [8][128]
    float* s_col = reinterpret_cast<float*>(smem + SM_COL);   // [2][256]

    // ---- async loader: one K-chunk into stage s ----
    auto load_chunk = [&](int c, int s) {
        const int kt = c * KCHUNK;
        const uint32_t base = sb + s * STAGEB;
        // A: 1024 16B units (its 0-1), B: 2048 units (its 2-5)
#pragma unroll
        for (int it = 0; it < 2; it++) {
            const int seg = it * 512 + tid;      // 0..1023
            const int row = seg >> 3;
            const int u   = seg & 7;
            cpasync16(base + row * PITCHB + u * 16, Aptr + (size_t)row * D + kt + u * 8);
        }
#pragma unroll
        for (int it = 0; it < 4; it++) {
            const int seg = it * 512 + tid;      // 0..2047
            const int row = seg >> 3;            // 0..255
            const int u   = seg & 7;
            cpasync16(base + A_TILEB + row * PITCHB + u * 16, Bptr + (size_t)row * D + kt + u * 8);
        }
        CP_COMMIT();
    };

    // ldmatrix lane-invariant offsets
    const int rA = (lid & 7) | (((lid >> 3) & 1) << 3);
    const int cBk = (lid >> 4) * 8;
    uint32_t aoff[4], boff[2];
#pragma unroll
    for (int mt = 0; mt < 4; mt++) aoff[mt] = (uint32_t)((wm*64 + mt*16 + rA) * PITCHB + cBk*2);
#pragma unroll
    for (int np = 0; np < 2; np++) boff[np] = (uint32_t)(A_TILEB + (wn*32 + np*16 + rA) * PITCHB + cBk*2);

    // stage sq norms
    if (tid < 128) sqi_s[tid] = g_sq[view][i0 + tid];
    else if (tid < 384) sqj_s[tid - 128] = g_sq[view][j0 + tid - 128];

    float acc[4][4][4];
#pragma unroll
    for (int a = 0; a < 4; a++)
#pragma unroll
        for (int b = 0; b < 4; b++)
#pragma unroll
            for (int q = 0; q < 4; q++) acc[a][b][q] = 0.f;

    load_chunk(0, 0);

    for (int c = 0; c < NCHUNK; c++) {
        const int s = c & 1;
        if (c + 1 < NCHUNK) { load_chunk(c + 1, s ^ 1); CP_WAIT(1); }
        else                { CP_WAIT(0); }
        __syncthreads();

        const uint32_t base = sb + s * STAGEB;
#pragma unroll
        for (int ks = 0; ks < KCHUNK / 16; ks++) {
            const uint32_t ko = ks * 32;
            uint32_t A[4][4], B[2][4];
#pragma unroll
            for (int mt = 0; mt < 4; mt++) ldsm4(A[mt], base + aoff[mt] + ko);
#pragma unroll
            for (int np = 0; np < 2; np++) ldsm4(B[np], base + boff[np] + ko);
#pragma unroll
            for (int mt = 0; mt < 4; mt++) {
#pragma unroll
                for (int nt = 0; nt < 4; nt++) {
                    const int np = nt >> 1, sel = nt & 1;
                    mma16816(acc[mt][nt], A[mt], B[np][sel], B[np][2 + sel]);
                }
            }
        }
        __syncthreads();
    }

    // ---- Epilogue ----
    const bool dsub = (wn < 4) ? diag0 : diag1;   // this warp's sub-tile diagonal?
    float rsum[4][2], csum[4][2];
#pragma unroll
    for (int q = 0; q < 4; q++) { rsum[q][0]=rsum[q][1]=0.f; csum[q][0]=csum[q][1]=0.f; }

#pragma unroll
    for (int mt = 0; mt < 4; mt++) {
        const int r0 = wm*64 + mt*16 + (lid >> 2);      // local row (and +8)
        const float sqr0 = sqi_s[r0], sqr1 = sqi_s[r0 + 8];
#pragma unroll
        for (int nt = 0; nt < 4; nt++) {
            const int c0 = wn*32 + nt*8 + 2*(lid & 3);  // col within 256
            const int cs0 = c0 & 127;                   // col within sub-tile
            const float sqc0 = sqj_s[c0], sqc1 = sqj_s[c0 + 1];
            const float* a = acc[mt][nt];
            float d2, d, e00, e01, e10, e11;
            d2 = fmaxf(sqr0 + sqc0 - 2.f*a[0], 0.f); d = fsqrt_approx(d2);
            e00 = (dsub && r0 == cs0) ? 0.f : __expf(-d);
            d2 = fmaxf(sqr0 + sqc1 - 2.f*a[1], 0.f); d = fsqrt_approx(d2);
            e01 = (dsub && r0 == cs0 + 1) ? 0.f : __expf(-d);
            d2 = fmaxf(sqr1 + sqc0 - 2.f*a[2], 0.f); d = fsqrt_approx(d2);
            e10 = (dsub && r0 + 8 == cs0) ? 0.f : __expf(-d);
            d2 = fmaxf(sqr1 + sqc1 - 2.f*a[3], 0.f); d = fsqrt_approx(d2);
            e11 = (dsub && r0 + 8 == cs0 + 1) ? 0.f : __expf(-d);
            rsum[mt][0] += e00 + e01;
            rsum[mt][1] += e10 + e11;
            csum[nt][0] += e00 + e10;
            csum[nt][1] += e01 + e11;
        }
    }

    // Row sums: reduce over 4 (lid&3) lanes; stage per wn.
#pragma unroll
    for (int mt = 0; mt < 4; mt++) {
        float v0 = rsum[mt][0], v1 = rsum[mt][1];
        v0 += __shfl_xor_sync(0xffffffffu, v0, 1); v0 += __shfl_xor_sync(0xffffffffu, v0, 2);
        v1 += __shfl_xor_sync(0xffffffffu, v1, 1); v1 += __shfl_xor_sync(0xffffffffu, v1, 2);
        if ((lid & 3) == 0) {
            const int r = wm*64 + mt*16 + (lid >> 2);
            s_row[wn*128 + r]     = v0;
            s_row[wn*128 + r + 8] = v1;
        }
    }
    // Col sums: reduce over 8 (lid>>2) groups; stage per wm.
#pragma unroll
    for (int nt = 0; nt < 4; nt++) {
        float u0 = csum[nt][0], u1 = csum[nt][1];
#pragma unroll
        for (int off = 4; off < 32; off <<= 1) {
            u0 += __shfl_xor_sync(0xffffffffu, u0, off);
            u1 += __shfl_xor_sync(0xffffffffu, u1, off);
        }
        if (lid < 4) {
            const int cc = wn*32 + nt*8 + 2*lid;
            s_col[wm*256 + cc]     = u0;
            s_col[wm*256 + cc + 1] = u1;
        }
    }
    __syncthreads();

    // Final writes. Rows: tid<128. Cols: tid in [128, 384).
    if (tid < 128) {
        const int r = tid;
        float rv1 = s_row[4*128 + r] + s_row[5*128 + r] + s_row[6*128 + r] + s_row[7*128 + r];
        g_part[view][tj1][i0 + r] = rv1;                       // sub1 always valid
        if (sub0_valid) {
            float rv0 = s_row[0*128 + r] + s_row[1*128 + r] + s_row[2*128 + r] + s_row[3*128 + r];
            g_part[view][tj0][i0 + r] = rv0;
        }
    } else if (tid < 384) {
        const int c = tid - 128;                               // 0..255
        const bool colvalid = (c < 128) ? (ti < tj0) : (ti < tj1);
        if (colvalid) {
            float cv = s_col[c] + s_col[256 + c];
            g_part[view][ti][j0 + c] = cv;
        }
    }
}

// ---------------------------------------------------------------------------
// Kernel 3: finalize with fp64 accumulation.
// ---------------------------------------------------------------------------
__global__ void finalize_kernel(float* __restrict__ out) {
    __shared__ double sh0[256], sh1[256], sh2[256];
    const int tid = threadIdx.x;
    double a = 0.0, e0 = 0.0, e1 = 0.0;
    for (int i = tid; i < N; i += 256) {
        a += (double)g_alignRow[i];
        float s0 = 0.f, s1 = 0.f;
#pragma unroll
        for (int c = 0; c < NT; c++) {
            s0 += g_part[0][c][i];
            s1 += g_part[1][c][i];
        }
        e0 += log((double)s0);
        e1 += log((double)s1);
    }
    sh0[tid] = a; sh1[tid] = e0; sh2[tid] = e1;
    __syncthreads();
    for (int off = 128; off > 0; off >>= 1) {
        if (tid < off) {
            sh0[tid] += sh0[tid + off];
            sh1[tid] += sh1[tid + off];
            sh2[tid] += sh2[tid + off];
        }
        __syncthreads();
    }
    if (tid == 0) {
        const double inv_n = 1.0 / (double)N;
        const double logm  = log((double)(N - 1));
        double align   = sh0[0] * inv_n;
        double entropy = 0.5 * ((sh1[0] * inv_n - logm) + (sh2[0] * inv_n - logm));
        out[0] = (float)(align + entropy);
    }
}

// ---------------------------------------------------------------------------
extern "C" void kernel_launch(void* const* d_in, const int* in_sizes, int n_in,
                              void* d_out, int out_size) {
    const float* v0 = (const float*)d_in[0];
    const float* v1 = (const float*)d_in[1];
    float* out = (float*)d_out;

    cudaFuncSetAttribute(gram_mma_kernel, cudaFuncAttributeMaxDynamicSharedMemorySize, SMEM_TOTAL);

    convert_kernel<<<N / 8, dim3(32, 8)>>>(v0, v1);
    gram_mma_kernel<<<dim3(NSUP, 1, 2), THREADS, SMEM_TOTAL>>>();
    finalize_kernel<<<1, 256>>>(out);
}

// round 9
// speedup vs baseline: 1.1086x; 1.0323x over previous
#include <cuda_runtime.h>
#include <cuda_bf16.h>
#include <math.h>
#include <stdint.h>

// loss = mean_i ||v0_i - v1_i|| + 0.5 * sum_views mean_i [ log(sum_{j!=i} exp(-d_ij)) - log(N-1) ]
// d_ij = max(sqrt(max(|zi|^2+|zj|^2-2 zi.zj, 0)), 1e-12)
//
// Gram via mma.sync pure bf16 (verified rel_err ~1.3e-5). Symmetric upper-tri
// 128x128 tiles; each tile feeds row AND col sums. MINIMAL-SYNC design:
// KCHUNK=128 (two chunks per tile), single operand stage, 4 barriers/tile,
// 128-MMA uninterrupted runs per warp. Cross-phase hiding via 2 CTAs/SM.

namespace {
constexpr int N  = 8192;
constexpr int D  = 256;
constexpr int BM = 128;
constexpr int NT = N / BM;               // 64
constexpr int NTRI = NT * (NT + 1) / 2;  // 2080

constexpr int KCHUNK  = 128;             // bf16 k per chunk (256B rows)
constexpr int NCHUNK  = D / KCHUNK;      // 2
constexpr int KSTEPS  = KCHUNK / 16;     // 8
constexpr int PITCHB  = 272;             // 256 payload + 16 pad (68 words ≡ 4 mod 32)
constexpr int TILEB   = BM * PITCHB;     // 34816 per operand
constexpr int STAGEB  = 2 * TILEB;       // 69632 (A + B), single stage
constexpr int SM_SQI  = STAGEB;          // 128 f32
constexpr int SM_SQJ  = SM_SQI + 512;    // 128 f32
constexpr int SM_ROW  = SM_SQJ + 512;    // [4][128] f32 = 2048
constexpr int SM_COL  = SM_ROW + 2048;   // [2][128] f32 = 1024
constexpr int SMEM_TOTAL = SM_COL + 1024 + 256;   // ~74KB -> 2 CTAs/SM
}

__device__ __align__(16) __nv_bfloat16 g_bf[2][N][D];
__device__ __align__(16) float g_sq[2][N];
__device__ __align__(16) float g_alignRow[N];
__device__ __align__(16) float g_part[2][NT][N];

// ---------------- PTX helpers (stable ISA only) -----------------------------
__device__ __forceinline__ uint32_t smem_u32(const void* p) {
    uint32_t a;
    asm("{ .reg .u64 t; cvta.to.shared.u64 t, %1; cvt.u32.u64 %0, t; }" : "=r"(a) : "l"(p));
    return a;
}
__device__ __forceinline__ void cpasync16(uint32_t dst, const void* src) {
    asm volatile("cp.async.cg.shared.global [%0], [%1], 16;" :: "r"(dst), "l"(src) : "memory");
}
#define CP_COMMIT()  asm volatile("cp.async.commit_group;" ::: "memory")
#define CP_WAIT0()   asm volatile("cp.async.wait_group 0;" ::: "memory")

__device__ __forceinline__ void ldsm4(uint32_t* r, uint32_t addr) {
    asm volatile("ldmatrix.sync.aligned.m8n8.x4.shared.b16 {%0,%1,%2,%3}, [%4];"
                 : "=r"(r[0]), "=r"(r[1]), "=r"(r[2]), "=r"(r[3]) : "r"(addr));
}
__device__ __forceinline__ void mma16816(float* c, const uint32_t* a, uint32_t b0, uint32_t b1) {
    asm volatile(
        "mma.sync.aligned.m16n8k16.row.col.f32.bf16.bf16.f32 "
        "{%0,%1,%2,%3}, {%4,%5,%6,%7}, {%8,%9}, {%0,%1,%2,%3};"
        : "+f"(c[0]), "+f"(c[1]), "+f"(c[2]), "+f"(c[3])
        : "r"(a[0]), "r"(a[1]), "r"(a[2]), "r"(a[3]), "r"(b0), "r"(b1));
}
__device__ __forceinline__ float fsqrt_approx(float x) {
    float r; asm("sqrt.approx.f32 %0, %1;" : "=f"(r) : "f"(x)); return r;
}

// ---------------------------------------------------------------------------
// Kernel 1: fp32 -> bf16; squared norms (fp32); align row norms.
// ---------------------------------------------------------------------------
__global__ void convert_kernel(const float* __restrict__ v0, const float* __restrict__ v1) {
    int row  = blockIdx.x * blockDim.y + threadIdx.y;
    int lane = threadIdx.x;
    const float4* r0 = reinterpret_cast<const float4*>(v0 + (size_t)row * D);
    const float4* r1 = reinterpret_cast<const float4*>(v1 + (size_t)row * D);
    __nv_bfloat162* h0 = reinterpret_cast<__nv_bfloat162*>(&g_bf[0][row][0]);
    __nv_bfloat162* h1 = reinterpret_cast<__nv_bfloat162*>(&g_bf[1][row][0]);

    float s0 = 0.f, s1 = 0.f, sd = 0.f;
#pragma unroll
    for (int c = lane; c < D / 4; c += 32) {
        float4 a = r0[c], b = r1[c];
        s0 += a.x*a.x + a.y*a.y + a.z*a.z + a.w*a.w;
        s1 += b.x*b.x + b.y*b.y + b.z*b.z + b.w*b.w;
        float dx=a.x-b.x, dy=a.y-b.y, dz=a.z-b.z, dw=a.w-b.w;
        sd += dx*dx + dy*dy + dz*dz + dw*dw;
        h0[2*c]   = __halves2bfloat162(__float2bfloat16(a.x), __float2bfloat16(a.y));
        h0[2*c+1] = __halves2bfloat162(__float2bfloat16(a.z), __float2bfloat16(a.w));
        h1[2*c]   = __halves2bfloat162(__float2bfloat16(b.x), __float2bfloat16(b.y));
        h1[2*c+1] = __halves2bfloat162(__float2bfloat16(b.z), __float2bfloat16(b.w));
    }
#pragma unroll
    for (int off = 16; off > 0; off >>= 1) {
        s0 += __shfl_down_sync(0xffffffffu, s0, off);
        s1 += __shfl_down_sync(0xffffffffu, s1, off);
        sd += __shfl_down_sync(0xffffffffu, sd, off);
    }
    if (lane == 0) {
        g_sq[0][row] = s0;
        g_sq[1][row] = s1;
        g_alignRow[row] = sqrtf(sd);
    }
}

// ---------------------------------------------------------------------------
// Kernel 2: symmetric Gram + exp(-d) row/col sums via mma.sync bf16.
// One CTA per upper-tri tile per view. 256 threads = 8 warps (2M x 4N).
// Two big chunk phases, single stage, 4 barriers/tile total.
// ---------------------------------------------------------------------------
__global__ __launch_bounds__(256, 2)
void gram_mma_kernel() {
    extern __shared__ char smem[];
    const uint32_t sb = smem_u32(smem);
    const int tid = threadIdx.x;
    const int lid = tid & 31;
    const int wid = tid >> 5;
    const int wm = wid >> 2;          // 0..1
    const int wn = wid & 3;           // 0..3
    const int view = blockIdx.z;

    // tile decode: l = tj*(tj+1)/2 + ti, ti <= tj
    const int l = blockIdx.x;
    int tj = (int)((sqrtf(8.f * (float)l + 1.f) - 1.f) * 0.5f);
    while ((tj + 1) * (tj + 2) / 2 <= l) ++tj;
    while (tj * (tj + 1) / 2 > l) --tj;
    const int ti = l - tj * (tj + 1) / 2;
    const int i0 = ti * BM;
    const int j0 = tj * BM;

    const __nv_bfloat16* __restrict__ Aptr = &g_bf[view][i0][0];
    const __nv_bfloat16* __restrict__ Bptr = &g_bf[view][j0][0];

    float* sqi_s = reinterpret_cast<float*>(smem + SM_SQI);
    float* sqj_s = reinterpret_cast<float*>(smem + SM_SQJ);
    float* s_row = reinterpret_cast<float*>(smem + SM_ROW);   // [4][128]
    float* s_col = reinterpret_cast<float*>(smem + SM_COL);   // [2][128]

    // stage sq norms (overlaps with first load)
    if (tid < 128) sqi_s[tid] = g_sq[view][i0 + tid];
    else           sqj_s[tid - 128] = g_sq[view][j0 + tid - 128];

    // ldmatrix lane-invariant offsets
    const int rA = (lid & 7) | (((lid >> 3) & 1) << 3);
    const int cBk = (lid >> 4) * 8;
    uint32_t aoff[4], boff[2];
#pragma unroll
    for (int mt = 0; mt < 4; mt++) aoff[mt] = (uint32_t)((wm*64 + mt*16 + rA) * PITCHB + cBk*2);
#pragma unroll
    for (int np = 0; np < 2; np++) boff[np] = (uint32_t)(TILEB + (wn*32 + np*16 + rA) * PITCHB + cBk*2);

    float acc[4][4][4];
#pragma unroll
    for (int a = 0; a < 4; a++)
#pragma unroll
        for (int b = 0; b < 4; b++)
#pragma unroll
            for (int q = 0; q < 4; q++) acc[a][b][q] = 0.f;

    for (int c = 0; c < NCHUNK; c++) {
        const int kt = c * KCHUNK;
        // burst load: A then B, 16 x 16B units per thread per operand
#pragma unroll
        for (int it = 0; it < 16; it++) {
            const int idx = it * 256 + tid;     // 0..4095
            const int row = idx >> 4;           // 0..255 -> A rows then B rows
            const int u   = idx & 15;           // 16B unit within 256B row
            const __nv_bfloat16* src = (row < 128)
                ? Aptr + (size_t)row * D + kt + u * 8
                : Bptr + (size_t)(row - 128) * D + kt + u * 8;
            const uint32_t dst = (row < 128)
                ? sb + row * PITCHB + u * 16
                : sb + TILEB + (row - 128) * PITCHB + u * 16;
            cpasync16(dst, src);
        }
        CP_COMMIT();
        CP_WAIT0();
        __syncthreads();

#pragma unroll
        for (int ks = 0; ks < KSTEPS; ks++) {
            const uint32_t ko = ks * 32;
            uint32_t A[4][4], B[2][4];
#pragma unroll
            for (int mt = 0; mt < 4; mt++) ldsm4(A[mt], sb + aoff[mt] + ko);
#pragma unroll
            for (int np = 0; np < 2; np++) ldsm4(B[np], sb + boff[np] + ko);
#pragma unroll
            for (int mt = 0; mt < 4; mt++) {
#pragma unroll
                for (int nt = 0; nt < 4; nt++) {
                    const int np = nt >> 1, sel = nt & 1;
                    mma16816(acc[mt][nt], A[mt], B[np][sel], B[np][2 + sel]);
                }
            }
        }
        if (c + 1 < NCHUNK) __syncthreads();   // buffer reuse guard
    }

    // ---- Epilogue: e = exp(-d); row sums + col sums ----
    const bool diag = (ti == tj);
    float rsum[4][2], csum[4][2];
#pragma unroll
    for (int q = 0; q < 4; q++) { rsum[q][0]=rsum[q][1]=0.f; csum[q][0]=csum[q][1]=0.f; }

#pragma unroll
    for (int mt = 0; mt < 4; mt++) {
        const int r0 = wm*64 + mt*16 + (lid >> 2);
        const float sqr0 = sqi_s[r0], sqr1 = sqi_s[r0 + 8];
#pragma unroll
        for (int nt = 0; nt < 4; nt++) {
            const int c0 = wn*32 + nt*8 + 2*(lid & 3);
            const float sqc0 = sqj_s[c0], sqc1 = sqj_s[c0 + 1];
            const float* a = acc[mt][nt];
            float d2, e00, e01, e10, e11;
            d2 = fmaxf(sqr0 + sqc0 - 2.f*a[0], 0.f);
            e00 = (diag && r0 == c0) ? 0.f : __expf(-fsqrt_approx(d2));
            d2 = fmaxf(sqr0 + sqc1 - 2.f*a[1], 0.f);
            e01 = (diag && r0 == c0 + 1) ? 0.f : __expf(-fsqrt_approx(d2));
            d2 = fmaxf(sqr1 + sqc0 - 2.f*a[2], 0.f);
            e10 = (diag && r0 + 8 == c0) ? 0.f : __expf(-fsqrt_approx(d2));
            d2 = fmaxf(sqr1 + sqc1 - 2.f*a[3], 0.f);
            e11 = (diag && r0 + 8 == c0 + 1) ? 0.f : __expf(-fsqrt_approx(d2));
            rsum[mt][0] += e00 + e01;
            rsum[mt][1] += e10 + e11;
            csum[nt][0] += e00 + e10;
            csum[nt][1] += e01 + e11;
        }
    }

    // Row sums: reduce over the 4 (lid&3) lanes.
#pragma unroll
    for (int mt = 0; mt < 4; mt++) {
        float v0 = rsum[mt][0], v1 = rsum[mt][1];
        v0 += __shfl_xor_sync(0xffffffffu, v0, 1); v0 += __shfl_xor_sync(0xffffffffu, v0, 2);
        v1 += __shfl_xor_sync(0xffffffffu, v1, 1); v1 += __shfl_xor_sync(0xffffffffu, v1, 2);
        if ((lid & 3) == 0) {
            const int r = wm*64 + mt*16 + (lid >> 2);
            s_row[wn*128 + r]     = v0;
            s_row[wn*128 + r + 8] = v1;
        }
    }
    // Col sums: reduce over the 8 (lid>>2) groups.
#pragma unroll
    for (int nt = 0; nt < 4; nt++) {
        float u0 = csum[nt][0], u1 = csum[nt][1];
#pragma unroll
        for (int off = 4; off < 32; off <<= 1) {
            u0 += __shfl_xor_sync(0xffffffffu, u0, off);
            u1 += __shfl_xor_sync(0xffffffffu, u1, off);
        }
        if (lid < 4) {
            const int cc = wn*32 + nt*8 + 2*lid;
            s_col[wm*128 + cc]     = u0;
            s_col[wm*128 + cc + 1] = u1;
        }
    }
    __syncthreads();

    if (tid < 128) {
        float rv = s_row[tid] + s_row[128 + tid] + s_row[256 + tid] + s_row[384 + tid];
        g_part[view][tj][i0 + tid] = rv;
        if (ti != tj) {
            float cv = s_col[tid] + s_col[128 + tid];
            g_part[view][ti][j0 + tid] = cv;
        }
    }
}

// ---------------------------------------------------------------------------
// Kernel 3: finalize with fp64 accumulation.
// ---------------------------------------------------------------------------
__global__ void finalize_kernel(float* __restrict__ out) {
    __shared__ double sh0[256], sh1[256], sh2[256];
    const int tid = threadIdx.x;
    double a = 0.0, e0 = 0.0, e1 = 0.0;
    for (int i = tid; i < N; i += 256) {
        a += (double)g_alignRow[i];
        float s0 = 0.f, s1 = 0.f;
#pragma unroll
        for (int c = 0; c < NT; c++) {
            s0 += g_part[0][c][i];
            s1 += g_part[1][c][i];
        }
        e0 += log((double)s0);
        e1 += log((double)s1);
    }
    sh0[tid] = a; sh1[tid] = e0; sh2[tid] = e1;
    __syncthreads();
    for (int off = 128; off > 0; off >>= 1) {
        if (tid < off) {
            sh0[tid] += sh0[tid + off];
            sh1[tid] += sh1[tid + off];
            sh2[tid] += sh2[tid + off];
        }
        __syncthreads();
    }
    if (tid == 0) {
        const double inv_n = 1.0 / (double)N;
        const double logm  = log((double)(N - 1));
        double align   = sh0[0] * inv_n;
        double entropy = 0.5 * ((sh1[0] * inv_n - logm) + (sh2[0] * inv_n - logm));
        out[0] = (float)(align + entropy);
    }
}

// ---------------------------------------------------------------------------
extern "C" void kernel_launch(void* const* d_in, const int* in_sizes, int n_in,
                              void* d_out, int out_size) {
    const float* v0 = (const float*)d_in[0];
    const float* v1 = (const float*)d_in[1];
    float* out = (float*)d_out;

    cudaFuncSetAttribute(gram_mma_kernel, cudaFuncAttributeMaxDynamicSharedMemorySize, SMEM_TOTAL);

    convert_kernel<<<N / 8, dim3(32, 8)>>>(v0, v1);
    gram_mma_kernel<<<dim3(NTRI, 1, 2), 256, SMEM_TOTAL>>>();
    finalize_kernel<<<1, 256>>>(out);
}